// round 1
// baseline (speedup 1.0000x reference)
#include <cuda_runtime.h>
#include <cuda_bf16.h>
#include <math.h>

// Problem constants
#define BATCH   2
#define SEQ     2048
#define DMODEL  2048
#define NHEADS  16
#define DK      128
#define ROWS    (BATCH * SEQ)          // 4096

// ---------------- scratch (static device globals: no runtime alloc) ----------
__device__ float g_Q[ROWS * DMODEL];
__device__ float g_K[ROWS * DMODEL];
__device__ float g_V[ROWS * DMODEL];
__device__ float g_AO[ROWS * DMODEL];

// ---------------- SGEMM: C[m,n] = sum_k A[m,k]*B[n,k] + bias[n] --------------
// A: [M,K] row-major, B: [N,K] row-major (i.e. C = A @ B^T), all fp32.
#define GBM 128
#define GBN 128
#define GBK 16

__global__ __launch_bounds__(256)
void sgemm_nt_bias(const float* __restrict__ A, const float* __restrict__ Bm,
                   const float* __restrict__ bias, float* __restrict__ C,
                   int M, int N, int K)
{
    __shared__ float As[GBK][GBM + 4];
    __shared__ float Bs[GBK][GBN + 4];

    const int tid = threadIdx.x;
    const int tx = tid & 15;
    const int ty = tid >> 4;
    const int m0 = blockIdx.y * GBM;
    const int n0 = blockIdx.x * GBN;

    float acc[8][8];
#pragma unroll
    for (int i = 0; i < 8; i++)
#pragma unroll
        for (int j = 0; j < 8; j++) acc[i][j] = 0.f;

    for (int k0 = 0; k0 < K; k0 += GBK) {
        // Load tiles: 128 rows x 16 cols = 512 float4 each, 2 per thread.
#pragma unroll
        for (int t = 0; t < 2; ++t) {
            int f = tid + t * 256;
            int row = f >> 2;            // 0..127
            int c4  = (f & 3) * 4;       // 0,4,8,12
            float4 av = *(const float4*)&A[(size_t)(m0 + row) * K + k0 + c4];
            As[c4 + 0][row] = av.x; As[c4 + 1][row] = av.y;
            As[c4 + 2][row] = av.z; As[c4 + 3][row] = av.w;
            float4 bv = *(const float4*)&Bm[(size_t)(n0 + row) * K + k0 + c4];
            Bs[c4 + 0][row] = bv.x; Bs[c4 + 1][row] = bv.y;
            Bs[c4 + 2][row] = bv.z; Bs[c4 + 3][row] = bv.w;
        }
        __syncthreads();

#pragma unroll
        for (int kk = 0; kk < GBK; ++kk) {
            float a[8], b[8];
            float4 a0 = *(float4*)&As[kk][ty * 8];
            float4 a1 = *(float4*)&As[kk][ty * 8 + 4];
            a[0]=a0.x; a[1]=a0.y; a[2]=a0.z; a[3]=a0.w;
            a[4]=a1.x; a[5]=a1.y; a[6]=a1.z; a[7]=a1.w;
            float4 b0 = *(float4*)&Bs[kk][tx * 8];
            float4 b1 = *(float4*)&Bs[kk][tx * 8 + 4];
            b[0]=b0.x; b[1]=b0.y; b[2]=b0.z; b[3]=b0.w;
            b[4]=b1.x; b[5]=b1.y; b[6]=b1.z; b[7]=b1.w;
#pragma unroll
            for (int i = 0; i < 8; i++)
#pragma unroll
                for (int j = 0; j < 8; j++)
                    acc[i][j] = fmaf(a[i], b[j], acc[i][j]);
        }
        __syncthreads();
    }

    // Epilogue with bias
#pragma unroll
    for (int i = 0; i < 8; i++) {
        int m = m0 + ty * 8 + i;
        float* crow = &C[(size_t)m * N + n0 + tx * 8];
        const float* brow = &bias[n0 + tx * 8];
        float4 r0, r1;
        r0.x = acc[i][0] + brow[0]; r0.y = acc[i][1] + brow[1];
        r0.z = acc[i][2] + brow[2]; r0.w = acc[i][3] + brow[3];
        r1.x = acc[i][4] + brow[4]; r1.y = acc[i][5] + brow[5];
        r1.z = acc[i][6] + brow[6]; r1.w = acc[i][7] + brow[7];
        *(float4*)&crow[0] = r0;
        *(float4*)&crow[4] = r1;
    }
}

// ---------------- RoPE (interleaved pairs, in place) -------------------------
__global__ __launch_bounds__(256)
void rope_kernel(float* __restrict__ buf)
{
    int idx = blockIdx.x * blockDim.x + threadIdx.x; // pair index
    const int total = ROWS * NHEADS * (DK / 2);
    if (idx >= total) return;
    int i   = idx & 63;            // freq index 0..63
    int h   = (idx >> 6) & 15;
    int row = idx >> 10;           // 0..4095
    int s   = row & (SEQ - 1);     // position

    float inv_freq = powf(10000.0f, -((float)(2 * i)) / 128.0f);
    float fr = (float)s * inv_freq;
    float c, sn;
    sincosf(fr, &sn, &c);

    float* p = buf + (size_t)row * DMODEL + h * DK + 2 * i;
    float e = p[0], o = p[1];
    p[0] = e * c - o * sn;
    p[1] = e * sn + o * c;
}

// ---------------- Flash attention (fp32, causal, online softmax) -------------
// Q,K,V,O layout: [b*S + s][h*128 + d]  (row stride DMODEL)
#define FA_BM 64
#define FA_BN 64
#define QS_STR 132
#define KS_STR 132
#define VS_STR 132
#define PS_STR 68

__global__ __launch_bounds__(256)
void flash_attn(const float* __restrict__ Q, const float* __restrict__ K,
                const float* __restrict__ V, float* __restrict__ O)
{
    extern __shared__ float sm[];
    float* Qs = sm;                       // 64*132
    float* Ks = Qs + 64 * QS_STR;         // 64*132
    float* Vs = Ks + 64 * KS_STR;         // 64*132
    float* Ps = Vs + 64 * VS_STR;         // 64*68
    float* scaleRow = Ps + 64 * PS_STR;   // 64
    float* lRow     = scaleRow + 64;      // 64

    const int tid  = threadIdx.x;
    const int tx   = tid & 15;
    const int ty   = tid >> 4;
    const int warp = tid >> 5;
    const int lane = tid & 31;

    const int qblk = blockIdx.x;          // 0..31
    const int bh   = blockIdx.y;          // 0..31
    const int b    = bh >> 4;
    const int h    = bh & 15;
    const int q0   = qblk * FA_BM;
    const size_t base = ((size_t)b * SEQ) * DMODEL + (size_t)h * DK;

    const float qscale = 0.08838834764831843f; // 1/sqrt(128)

    // Load Q tile (pre-scaled)
    for (int f = tid; f < 64 * 32; f += 256) {
        int r = f >> 5, c4 = (f & 31) * 4;
        float4 qv = *(const float4*)&Q[base + (size_t)(q0 + r) * DMODEL + c4];
        qv.x *= qscale; qv.y *= qscale; qv.z *= qscale; qv.w *= qscale;
        *(float4*)&Qs[r * QS_STR + c4] = qv;
    }

    float m_i[4], l_i[4];
#pragma unroll
    for (int i = 0; i < 4; i++) { m_i[i] = -INFINITY; l_i[i] = 0.f; }
    float o[8][4];
#pragma unroll
    for (int i = 0; i < 8; i++)
#pragma unroll
        for (int j = 0; j < 4; j++) o[i][j] = 0.f;

    __syncthreads();

    const int nblk = qblk + 1;
    for (int jb = 0; jb < nblk; ++jb) {
        const int k0 = jb * FA_BN;
        // Load K,V tiles
        for (int f = tid; f < 64 * 32; f += 256) {
            int r = f >> 5, c4 = (f & 31) * 4;
            *(float4*)&Ks[r * KS_STR + c4] =
                *(const float4*)&K[base + (size_t)(k0 + r) * DMODEL + c4];
            *(float4*)&Vs[r * VS_STR + c4] =
                *(const float4*)&V[base + (size_t)(k0 + r) * DMODEL + c4];
        }
        __syncthreads();

        // S tile: rows 4*ty+i, cols tx + 16*j
        float sacc[4][4];
#pragma unroll
        for (int i = 0; i < 4; i++)
#pragma unroll
            for (int j = 0; j < 4; j++) sacc[i][j] = 0.f;

#pragma unroll 8
        for (int kk = 0; kk < 128; kk += 4) {
            float4 qv[4], kv[4];
#pragma unroll
            for (int i = 0; i < 4; i++)
                qv[i] = *(float4*)&Qs[(4 * ty + i) * QS_STR + kk];
#pragma unroll
            for (int j = 0; j < 4; j++)
                kv[j] = *(float4*)&Ks[(tx + 16 * j) * KS_STR + kk];
#pragma unroll
            for (int i = 0; i < 4; i++)
#pragma unroll
                for (int j = 0; j < 4; j++) {
                    sacc[i][j] = fmaf(qv[i].x, kv[j].x, sacc[i][j]);
                    sacc[i][j] = fmaf(qv[i].y, kv[j].y, sacc[i][j]);
                    sacc[i][j] = fmaf(qv[i].z, kv[j].z, sacc[i][j]);
                    sacc[i][j] = fmaf(qv[i].w, kv[j].w, sacc[i][j]);
                }
        }

        // Causal mask (only the diagonal block needs it)
        if (jb == qblk) {
#pragma unroll
            for (int i = 0; i < 4; i++) {
                int qrow = q0 + 4 * ty + i;
#pragma unroll
                for (int j = 0; j < 4; j++) {
                    int kcol = k0 + tx + 16 * j;
                    if (kcol > qrow) sacc[i][j] = -INFINITY;
                }
            }
        }

        // Online softmax per row (replicated across 16 lanes of the row group)
#pragma unroll
        for (int i = 0; i < 4; i++) {
            float pm = fmaxf(fmaxf(sacc[i][0], sacc[i][1]),
                             fmaxf(sacc[i][2], sacc[i][3]));
#pragma unroll
            for (int off = 8; off >= 1; off >>= 1)
                pm = fmaxf(pm, __shfl_xor_sync(0xffffffffu, pm, off));
            float mnew = fmaxf(m_i[i], pm);
            float sc = __expf(m_i[i] - mnew);
            float psum = 0.f;
#pragma unroll
            for (int j = 0; j < 4; j++) {
                float p = __expf(sacc[i][j] - mnew);
                sacc[i][j] = p;
                psum += p;
            }
#pragma unroll
            for (int off = 8; off >= 1; off >>= 1)
                psum += __shfl_xor_sync(0xffffffffu, psum, off);
            l_i[i] = l_i[i] * sc + psum;
            m_i[i] = mnew;
            if (tx == 0) scaleRow[4 * ty + i] = sc;
#pragma unroll
            for (int j = 0; j < 4; j++)
                Ps[(4 * ty + i) * PS_STR + tx + 16 * j] = sacc[i][j];
        }
        __syncthreads();

        // O = O * scale + P @ V. Thread owns rows 8*warp..+7, cols 4*lane..+3.
#pragma unroll
        for (int i = 0; i < 8; i++) {
            float sc = scaleRow[8 * warp + i];
#pragma unroll
            for (int j = 0; j < 4; j++) o[i][j] *= sc;
        }
#pragma unroll 4
        for (int k = 0; k < 64; k += 4) {
            float4 vv[4];
#pragma unroll
            for (int kk = 0; kk < 4; kk++)
                vv[kk] = *(float4*)&Vs[(k + kk) * VS_STR + 4 * lane];
#pragma unroll
            for (int i = 0; i < 8; i++) {
                float4 pv = *(float4*)&Ps[(8 * warp + i) * PS_STR + k];
                o[i][0] = fmaf(pv.x, vv[0].x, o[i][0]);
                o[i][1] = fmaf(pv.x, vv[0].y, o[i][1]);
                o[i][2] = fmaf(pv.x, vv[0].z, o[i][2]);
                o[i][3] = fmaf(pv.x, vv[0].w, o[i][3]);
                o[i][0] = fmaf(pv.y, vv[1].x, o[i][0]);
                o[i][1] = fmaf(pv.y, vv[1].y, o[i][1]);
                o[i][2] = fmaf(pv.y, vv[1].z, o[i][2]);
                o[i][3] = fmaf(pv.y, vv[1].w, o[i][3]);
                o[i][0] = fmaf(pv.z, vv[2].x, o[i][0]);
                o[i][1] = fmaf(pv.z, vv[2].y, o[i][1]);
                o[i][2] = fmaf(pv.z, vv[2].z, o[i][2]);
                o[i][3] = fmaf(pv.z, vv[2].w, o[i][3]);
                o[i][0] = fmaf(pv.w, vv[3].x, o[i][0]);
                o[i][1] = fmaf(pv.w, vv[3].y, o[i][1]);
                o[i][2] = fmaf(pv.w, vv[3].z, o[i][2]);
                o[i][3] = fmaf(pv.w, vv[3].w, o[i][3]);
            }
        }
        __syncthreads();
    }

    // Publish l per row, then normalize + store
    if (tx == 0) {
#pragma unroll
        for (int i = 0; i < 4; i++) lRow[4 * ty + i] = l_i[i];
    }
    __syncthreads();

#pragma unroll
    for (int i = 0; i < 8; i++) {
        int r = 8 * warp + i;
        float inv = 1.0f / lRow[r];
        float4 ov;
        ov.x = o[i][0] * inv; ov.y = o[i][1] * inv;
        ov.z = o[i][2] * inv; ov.w = o[i][3] * inv;
        *(float4*)&O[base + (size_t)(q0 + r) * DMODEL + 4 * lane] = ov;
    }
}

// ---------------- launch ------------------------------------------------------
extern "C" void kernel_launch(void* const* d_in, const int* in_sizes, int n_in,
                              void* d_out, int out_size)
{
    const float* x    = (const float*)d_in[0];
    const float* wq_w = (const float*)d_in[1];
    const float* wq_b = (const float*)d_in[2];
    const float* wk_w = (const float*)d_in[3];
    const float* wk_b = (const float*)d_in[4];
    const float* wv_w = (const float*)d_in[5];
    const float* wv_b = (const float*)d_in[6];
    const float* wo_w = (const float*)d_in[7];
    const float* wo_b = (const float*)d_in[8];
    float* out = (float*)d_out;

    float *qb, *kb, *vb, *ab;
    cudaGetSymbolAddress((void**)&qb, g_Q);
    cudaGetSymbolAddress((void**)&kb, g_K);
    cudaGetSymbolAddress((void**)&vb, g_V);
    cudaGetSymbolAddress((void**)&ab, g_AO);

    dim3 ggrid(DMODEL / GBN, ROWS / GBM);   // (16, 32)
    sgemm_nt_bias<<<ggrid, 256>>>(x, wq_w, wq_b, qb, ROWS, DMODEL, DMODEL);
    sgemm_nt_bias<<<ggrid, 256>>>(x, wk_w, wk_b, kb, ROWS, DMODEL, DMODEL);
    sgemm_nt_bias<<<ggrid, 256>>>(x, wv_w, wv_b, vb, ROWS, DMODEL, DMODEL);

    int pairs = ROWS * NHEADS * (DK / 2);
    int rblocks = (pairs + 255) / 256;
    rope_kernel<<<rblocks, 256>>>(qb);
    rope_kernel<<<rblocks, 256>>>(kb);

    size_t fa_smem = (size_t)(3 * 64 * 132 + 64 * 68 + 128) * sizeof(float);
    cudaFuncSetAttribute(flash_attn, cudaFuncAttributeMaxDynamicSharedMemorySize,
                         (int)fa_smem);
    dim3 fgrid(SEQ / FA_BM, BATCH * NHEADS); // (32, 32)
    flash_attn<<<fgrid, 256, fa_smem>>>(qb, kb, vb, ab);

    sgemm_nt_bias<<<ggrid, 256>>>(ab, wo_w, wo_b, out, ROWS, DMODEL, DMODEL);
}